// round 5
// baseline (speedup 1.0000x reference)
#include <cuda_runtime.h>
#include <math.h>

// Elman RNN, fp32. B=128, S=1024, I=256, H=512, O=256, N_TARGETS=1.
// Phase A: P[t][j][b] (fma2-packed GEMM)
// Phase B: persistent, 128 CTAs = 8 j-tiles(64) x 16 CTA-pairs.
//          Each CTA runs TWO independent batch chains (4 b each), interleaved
//          so each chain's h-exchange latency hides behind the other's compute.
// Phase C: output = h_T @ W_h2o^T + b_h2o ; hidden appended if requested.

typedef unsigned long long ull;

namespace {
constexpr int S = 1024, B = 128, I = 256, H = 512, O = 256;
constexpr int NJ = 8;                 // j-tiles (barrier arrivals per group)
constexpr int JT = 64;                // j per CTA
constexpr int BG = 4;                 // b per chain-group
constexpr int NBG = B / BG;           // 32 groups
constexpr int GSZ = H * BG;           // 2048 floats per group h slab
constexpr int PPAD = 72;              // partial b-row stride
constexpr int P_S_FLOATS = 8 * BG * PPAD;          // 2304
constexpr int SMEM_B_FLOATS = H * JT + 2 * GSZ + P_S_FLOATS;
constexpr int SMEM_B_BYTES = SMEM_B_FLOATS * 4;    // ~153 KB
}

__device__ float g_P[(size_t)S * H * B];     // [t][j][b] pre-activations
__device__ float g_H[2][NBG * GSZ];          // ping-pong h: [par][grp][k][4b]
__device__ struct { unsigned v; unsigned pad[31]; } g_bar[NBG];

__device__ __forceinline__ ull pack2(float x) {
    ull r;
    asm("mov.b64 %0, {%1, %1};" : "=l"(r) : "f"(x));
    return r;
}
__device__ __forceinline__ float2 unpack2(ull v) {
    float2 r;
    asm("mov.b64 {%0, %1}, %2;" : "=f"(r.x), "=f"(r.y) : "l"(v));
    return r;
}
__device__ __forceinline__ void fma2(ull& d, ull a, ull b) {
    asm("fma.rn.f32x2 %0, %1, %2, %0;" : "+l"(d) : "l"(a), "l"(b));
}
__device__ __forceinline__ void spin_ctr(unsigned* ctr, unsigned target) {
    unsigned v;
    do {
        asm volatile("ld.acquire.gpu.u32 %0, [%1];"
                     : "=r"(v) : "l"(ctr) : "memory");
    } while (v < target);
}
__device__ __forceinline__ void arrive_ctr(unsigned* ctr) {
    asm volatile("red.release.gpu.global.add.u32 [%0], 1;" :: "l"(ctr) : "memory");
}

// ---------------- Phase A: pre-activation GEMM (fma2-packed) ----------------
// grid (S, H/128), 256 threads. CTA: 128 j x 128 b for one t, K=I=256.
__global__ void __launch_bounds__(256) phaseA_kernel(
    const float* __restrict__ seq, const float* __restrict__ Wi2h,
    const float* __restrict__ bi2h) {
    const int t = blockIdx.x;
    const int j0 = blockIdx.y * 128;
    const int tid = threadIdx.x;
    const int tx = tid & 15;   // 8 b per thread
    const int ty = tid >> 4;   // 8 j per thread (4 fma2 pairs)
    __shared__ float sh_a[16 * 132];  // [k][j], padded
    __shared__ float sh_b[16 * 132];  // [k][b], padded
    ull acc[4][8];
#pragma unroll
    for (int r = 0; r < 4; r++)
#pragma unroll
        for (int c = 0; c < 8; c++) acc[r][c] = 0;

    for (int k0 = 0; k0 < I; k0 += 16) {
        __syncthreads();
#pragma unroll
        for (int q = 0; q < 2; q++) {
            int idx = tid + q * 256;  // 0..511
            int j = idx >> 2, kq = idx & 3;
            float4 v = *(const float4*)(Wi2h + (size_t)(j0 + j) * (I + H) + k0 + kq * 4);
            sh_a[(kq * 4 + 0) * 132 + j] = v.x;
            sh_a[(kq * 4 + 1) * 132 + j] = v.y;
            sh_a[(kq * 4 + 2) * 132 + j] = v.z;
            sh_a[(kq * 4 + 3) * 132 + j] = v.w;
        }
#pragma unroll
        for (int q = 0; q < 2; q++) {
            int idx = tid + q * 256;
            int b = idx >> 2, kq = idx & 3;
            float4 v = *(const float4*)(seq + (size_t)b * (S * I) + (size_t)t * I + k0 + kq * 4);
            sh_b[(kq * 4 + 0) * 132 + b] = v.x;
            sh_b[(kq * 4 + 1) * 132 + b] = v.y;
            sh_b[(kq * 4 + 2) * 132 + b] = v.z;
            sh_b[(kq * 4 + 3) * 132 + b] = v.w;
        }
        __syncthreads();
#pragma unroll
        for (int k = 0; k < 16; k++) {
            ulonglong2 a01 = *(const ulonglong2*)(sh_a + k * 132 + ty * 8);
            ulonglong2 a23 = *(const ulonglong2*)(sh_a + k * 132 + ty * 8 + 4);
            float4 b0 = *(const float4*)(sh_b + k * 132 + tx * 8);
            float4 b1 = *(const float4*)(sh_b + k * 132 + tx * 8 + 4);
            ull bb[8] = {pack2(b0.x), pack2(b0.y), pack2(b0.z), pack2(b0.w),
                         pack2(b1.x), pack2(b1.y), pack2(b1.z), pack2(b1.w)};
#pragma unroll
            for (int c = 0; c < 8; c++) {
                fma2(acc[0][c], a01.x, bb[c]);
                fma2(acc[1][c], a01.y, bb[c]);
                fma2(acc[2][c], a23.x, bb[c]);
                fma2(acc[3][c], a23.y, bb[c]);
            }
        }
    }
    // epilogue: unpack j-pairs, add bias, write P[t][j][b]
#pragma unroll
    for (int r = 0; r < 4; r++) {
        int j = j0 + ty * 8 + r * 2;
        float bj0 = bi2h[j], bj1 = bi2h[j + 1];
        float lo[8], hi[8];
#pragma unroll
        for (int c = 0; c < 8; c++) {
            float2 f = unpack2(acc[r][c]);
            lo[c] = f.x + bj0;
            hi[c] = f.y + bj1;
        }
        float* op0 = g_P + (size_t)t * (H * B) + (size_t)j * B + tx * 8;
        float* op1 = op0 + B;
        *(float4*)op0 = make_float4(lo[0], lo[1], lo[2], lo[3]);
        *(float4*)(op0 + 4) = make_float4(lo[4], lo[5], lo[6], lo[7]);
        *(float4*)op1 = make_float4(hi[0], hi[1], hi[2], hi[3]);
        *(float4*)(op1 + 4) = make_float4(hi[4], hi[5], hi[6], hi[7]);
    }
}

// ---------------- Phase B: persistent recurrence, 2 interleaved chains ------
__global__ void __launch_bounds__(256) phaseB_kernel(const float* __restrict__ Wi2h) {
    extern __shared__ float smem[];
    float* w_s = smem;                     // [512 k][64 j]
    float* h_sA = smem + H * JT;           // [512 k][4 b]
    float* h_sB = h_sA + GSZ;
    float* p_s = h_sB + GSZ;               // [8 kz][4 b (stride 72)][64 j]

    const int u = blockIdx.x & 15;         // CTA-pair index
    const int jj = blockIdx.x >> 4;
    const int j0 = jj * JT;
    const int gA = u * 2, gB = u * 2 + 1;
    const int tid = threadIdx.x;
    const int kz = tid >> 5;               // warp = k-slice of 64
    const int lane = tid & 31;
    const int ty = lane >> 2;              // 8 j per thread (4 fma2 pairs)
    const int tx = lane & 3;               // 1 b per thread
    const int jl = tid >> 2, bl = tid & 3; // reducer mapping (1 output/thread)

    // Load Wh transposed: w_s[k][j] = Wi2h[(j0+j)*(I+H) + I + k]
#pragma unroll
    for (int q = 0; q < 32; q++) {
        int idx = tid + q * 256;           // 0..8191 float4 slots
        int j = idx >> 7, k4 = idx & 127;
        float4 v = *(const float4*)(Wi2h + (size_t)(j0 + j) * (I + H) + I + k4 * 4);
        w_s[(k4 * 4 + 0) * JT + j] = v.x;
        w_s[(k4 * 4 + 1) * JT + j] = v.y;
        w_s[(k4 * 4 + 2) * JT + j] = v.z;
        w_s[(k4 * 4 + 3) * JT + j] = v.w;
    }

    unsigned* ctrA = &g_bar[gA].v;
    unsigned* ctrB = &g_bar[gB].v;
    const float* wp = w_s + kz * 64 * JT + ty * 8;
    const float* hpA = h_sA + kz * 64 * BG + tx;
    const float* hpB = h_sB + kz * 64 * BG + tx;

    for (int t = 0; t < S; t++) {
        // P prefetch for both chains (independent of barrier)
        const float* pPt = g_P + (size_t)t * (H * B) + (size_t)(j0 + jl) * B;
        float pA = pPt[gA * BG + bl];
        float pB = pPt[gB * BG + bl];

        // wait for peers' h(t) writes (fast path: satisfied during prev iter)
        if (tid == 0) spin_ctr(ctrA, (unsigned)t * NJ);
        else if (tid == 32) spin_ctr(ctrB, (unsigned)t * NJ);
        __syncthreads();

        // stage both chains' h slabs (coalesced, MLP-overlapped)
        const float4* rA = (const float4*)(g_H[t & 1] + gA * GSZ);
        const float4* rB = (const float4*)(g_H[t & 1] + gB * GSZ);
        float4 vA0 = rA[tid], vA1 = rA[tid + 256];
        float4 vB0 = rB[tid], vB1 = rB[tid + 256];
        ((float4*)h_sA)[tid] = vA0;
        ((float4*)h_sA)[tid + 256] = vA1;
        ((float4*)h_sB)[tid] = vB0;
        ((float4*)h_sB)[tid + 256] = vB1;
        __syncthreads();

        // ---- chain A compute ----
        {
            ull a0 = 0, a1 = 0, a2 = 0, a3 = 0;
#pragma unroll 16
            for (int kk = 0; kk < 64; kk++) {
                ulonglong2 wA = *(const ulonglong2*)(wp + kk * JT);
                ulonglong2 wB = *(const ulonglong2*)(wp + kk * JT + 4);
                ull hh = pack2(hpA[kk * BG]);
                fma2(a0, wA.x, hh);
                fma2(a1, wA.y, hh);
                fma2(a2, wB.x, hh);
                fma2(a3, wB.y, hh);
            }
            float* base = p_s + kz * (BG * PPAD) + tx * PPAD + ty * 8;
            *(ull*)(base + 0) = a0;
            *(ull*)(base + 2) = a1;
            *(ull*)(base + 4) = a2;
            *(ull*)(base + 6) = a3;
        }
        __syncthreads();
        {
            float s = pA;
#pragma unroll
            for (int z = 0; z < 8; z++) s += p_s[z * (BG * PPAD) + bl * PPAD + jl];
            g_H[(t + 1) & 1][gA * GSZ + j0 * BG + tid] = tanhf(s);
        }
        __syncthreads();
        if (tid == 0) arrive_ctr(ctrA);

        // ---- chain B compute (hides chain A's exchange latency) ----
        {
            ull a0 = 0, a1 = 0, a2 = 0, a3 = 0;
#pragma unroll 16
            for (int kk = 0; kk < 64; kk++) {
                ulonglong2 wA = *(const ulonglong2*)(wp + kk * JT);
                ulonglong2 wB = *(const ulonglong2*)(wp + kk * JT + 4);
                ull hh = pack2(hpB[kk * BG]);
                fma2(a0, wA.x, hh);
                fma2(a1, wA.y, hh);
                fma2(a2, wB.x, hh);
                fma2(a3, wB.y, hh);
            }
            float* base = p_s + kz * (BG * PPAD) + tx * PPAD + ty * 8;
            *(ull*)(base + 0) = a0;
            *(ull*)(base + 2) = a1;
            *(ull*)(base + 4) = a2;
            *(ull*)(base + 6) = a3;
        }
        __syncthreads();
        {
            float s = pB;
#pragma unroll
            for (int z = 0; z < 8; z++) s += p_s[z * (BG * PPAD) + bl * PPAD + jl];
            g_H[(t + 1) & 1][gB * GSZ + j0 * BG + tid] = tanhf(s);
        }
        __syncthreads();
        if (tid == 0) arrive_ctr(ctrB);
    }
}

// ---------------- Phase C: output projection + hidden emit ----------------
__global__ void __launch_bounds__(256) phaseC_kernel(
    const float* __restrict__ Wh2o, const float* __restrict__ bh2o,
    float* __restrict__ out, int out_size) {
    const float* hfin = g_H[S & 1];            // parity 0 after 1024 steps
    int idx = blockIdx.x * 256 + threadIdx.x;  // 0..32767
    int o = idx >> 7, b = idx & 127;
    const float* hb = hfin + (b >> 2) * GSZ + (b & 3);
    float acc = bh2o[o];
#pragma unroll 8
    for (int k = 0; k < H; k++)
        acc = fmaf(hb[k * BG], __ldg(Wh2o + (size_t)o * H + k), acc);
    int oidx = b * O + o;                      // output (B,1,O)
    if (oidx < out_size) out[oidx] = acc;
    if (out_size >= B * O + B * H) {
#pragma unroll
        for (int q = 0; q < 2; q++) {
            int e = idx + q * (B * O);         // 0..65535
            int hbk = e >> 9, hk = e & 511;
            out[B * O + e] = hfin[(hbk >> 2) * GSZ + hk * BG + (hbk & 3)];
        }
    }
}

extern "C" void kernel_launch(void* const* d_in, const int* in_sizes, int n_in,
                              void* d_out, int out_size) {
    const float* seq  = (const float*)d_in[0];
    const float* Wi2h = (const float*)d_in[1];
    const float* bi2h = (const float*)d_in[2];
    const float* Wh2o = (const float*)d_in[3];
    const float* bh2o = (const float*)d_in[4];
    float* out = (float*)d_out;

    cudaFuncSetAttribute(phaseB_kernel,
                         cudaFuncAttributeMaxDynamicSharedMemorySize, SMEM_B_BYTES);

    void* pBar = nullptr;
    cudaGetSymbolAddress(&pBar, g_bar);
    cudaMemsetAsync(pBar, 0, sizeof(g_bar), 0);
    void* pH = nullptr;
    cudaGetSymbolAddress(&pH, g_H);
    cudaMemsetAsync(pH, 0, (size_t)NBG * GSZ * sizeof(float), 0);  // h(0) = 0

    phaseA_kernel<<<dim3(S, H / 128), 256>>>(seq, Wi2h, bi2h);
    phaseB_kernel<<<128, 256, SMEM_B_BYTES>>>(Wi2h);
    phaseC_kernel<<<(B * O) / 256, 256>>>(Wh2o, bh2o, out, out_size);
}